// round 15
// baseline (speedup 1.0000x reference)
#include <cuda_runtime.h>
#include <cstdint>

// ---------------------------------------------------------------------------
// CTC loss (forward, sum over batch, zero_infinity) on GB300 — single fused
// kernel with WARP SPECIALIZATION. One CTA of 160 threads per batch element:
//   warps 0-3 (tid 0..127): compute. Thread tid owns trellis columns 2*tid
//     (blank: lse2, never skips) and 2*tid+1 (label: lse3). Log2-domain lse,
//     exact median-of-3 (ex2 args <= 0: overflow/NaN free). Per-step sync =
//     named barrier (bar.sync 1,128). Cross-warp halo via parity smem.
//   warp 4 (tid 128..159): producer. Issues ALL emit gathers (scattered
//     cp.async 4B) into a 4-chunk x 8-row smem ring; signals full[c]
//     (mbarrier, count=32) after cp.async.wait_all; paced by empty[c]
//     (count=1, consumer tid0 arrives after each chunk).
// Consumers pay one try_wait per 8 steps; zero gather work on compute warps.
// ---------------------------------------------------------------------------

#define NEGF (-1.0e30f)
#define LOG2E 1.4426950408889634f
#define LN2   0.6931471805599453f
#define TPB   160
#define NCW   4                           // compute warps
#define CH    8                           // rows per chunk
#define NCH   4                           // chunks in ring
#define RROWS 32

__device__ float g_loss[8192];
__device__ unsigned g_done;

__device__ __forceinline__ float ex2f(float x) {
    float r; asm("ex2.approx.f32 %0, %1;" : "=f"(r) : "f"(x)); return r;
}
__device__ __forceinline__ float lg2f(float x) {
    float r; asm("lg2.approx.f32 %0, %1;" : "=f"(r) : "f"(x)); return r;
}
__device__ __forceinline__ void cp4(uint32_t dst, const float* src) {
    asm volatile("cp.async.ca.shared.global [%0], [%1], 4;"
                 :: "r"(dst), "l"(src) : "memory");
}
__device__ __forceinline__ void cp_wait_all() {
    asm volatile("cp.async.wait_all;" ::: "memory");
}
__device__ __forceinline__ void mbar_init(uint32_t a, unsigned cnt) {
    asm volatile("mbarrier.init.shared.b64 [%0], %1;" :: "r"(a), "r"(cnt) : "memory");
}
__device__ __forceinline__ void mbar_arrive(uint32_t a) {
    asm volatile("mbarrier.arrive.shared.b64 _, [%0];" :: "r"(a) : "memory");
}
__device__ __forceinline__ void mbar_wait(uint32_t a, unsigned parity) {
    asm volatile(
        "{\n\t.reg .pred P;\n"
        "WAIT_%=:\n\t"
        "mbarrier.try_wait.parity.acquire.cta.shared::cta.b64 P, [%0], %1, 0x989680;\n\t"
        "@P bra.uni DONE_%=;\n\t"
        "bra.uni WAIT_%=;\n"
        "DONE_%=:\n\t}"
        :: "r"(a), "r"(parity) : "memory");
}
__device__ __forceinline__ void cbar() {            // compute-warp barrier
    asm volatile("bar.sync 1, 128;" ::: "memory");
}

// log2-domain lse3, exact median-of-3 (both ex2 args <= 0).
__device__ __forceinline__ float lse3_2(float a0, float a1, float a2) {
    const float mx01 = fmaxf(a0, a1);
    const float mn01 = fminf(a0, a1);
    const float mx   = fmaxf(mx01, a2);
    const float md   = fmaxf(mn01, fminf(mx01, a2));
    const float mn   = fminf(mn01, a2);
    return mx + lg2f(1.0f + ex2f(md - mx) + ex2f(mn - mx));
}
// log2-domain lse2.
__device__ __forceinline__ float lse2_2(float a0, float a1) {
    const float mx = fmaxf(a0, a1);
    const float mn = fminf(a0, a1);
    return mx + lg2f(1.0f + ex2f(mn - mx));
}

__global__ void __launch_bounds__(TPB, 1)
ctc_fused_kernel(const float* __restrict__ logp,
                 const int*   __restrict__ targets,
                 const int*   __restrict__ input_lens,
                 const int*   __restrict__ target_lens,
                 float* __restrict__ out,
                 int B, int C, int S)
{
    __shared__ __align__(16) float ring_l[RROWS][128];   // label logp, 16 KB
    __shared__ __align__(16) float ring_b[RROWS];        // blank logp (broadcast)
    __shared__ __align__(8)  unsigned long long mbar[8]; // full[0..3], empty[0..3]
    __shared__ float halo_s[2][NCW];
    __shared__ float fin[2];
    __shared__ int   s_last;

    const int b    = blockIdx.x;
    const int tid  = threadIdx.x;
    const int lane = tid & 31;
    const int w    = tid >> 5;
    const unsigned FULL = 0xffffffffu;

    const int tl = target_lens[b];
    const int il = input_lens[b];
    const int Lb = 2 * tl + 1;
    const int Rr = (il - 1) / 32;          // full 32-step rounds

    const size_t strideT = (size_t)B * C;
    const float* rowbase = logp + (size_t)b * C;

    const uint32_t rl0 = (uint32_t)__cvta_generic_to_shared(&ring_l[0][0]);
    const uint32_t rb0 = (uint32_t)__cvta_generic_to_shared(&ring_b[0]);
    const uint32_t mb0 = (uint32_t)__cvta_generic_to_shared(&mbar[0]);

    if (tid == 0) {
#pragma unroll
        for (int c = 0; c < 4; ++c) mbar_init(mb0 + c * 8u, 32u);       // full
#pragma unroll
        for (int c = 0; c < 4; ++c) mbar_init(mb0 + (4 + c) * 8u, 1u);  // empty
        fin[1] = NEGF;
        s_last = 0;
    }

    if (w < NCW) {
        // ===================== COMPUTE PATH (tids 0..127) =====================
        // Label + skip flag for odd column l1 = 2*tid+1 (even col never skips).
        int  e1  = 0;
        bool sk1 = false;
        if (tid < S) {
            e1 = targets[b * S + tid];
            const int l1 = 2 * tid + 1;
            if (l1 >= 3 && l1 < Lb) sk1 = (e1 != targets[b * S + tid - 1]);
        }
        const float* pl = rowbase + e1;

        // t = 0 init: columns 0,1 (thread 0); all else -1e30.
        float la0 = NEGF, la1 = NEGF;
        if (tid == 0) {
            la0 = rowbase[0] * LOG2E;
            la1 = pl[0] * LOG2E;
        }
        if (lane == 31) halo_s[0][w] = la1;   // parity 0, read at t = 1

        __syncthreads();                      // mbar init + halo published

        float erl = 0.0f, erb = 0.0f;
        if (Rr > 0) {
            mbar_wait(mb0 + 0u, 0u);          // full[0], 1st completion
            erl = ring_l[0][tid];             // row 1 staged
            erb = ring_b[0];
        }

        int tb = 1;
        for (int r = 0; r < Rr; ++r) {
#pragma unroll
            for (int c = 0; c < 4; ++c) {
                // Ensure next chunk resident (staging at j=7 touches it).
                const unsigned pn = (unsigned)(((c == 3) ? (r + 1) : r) & 1);
                mbar_wait(mb0 + (unsigned)((c + 1) & 3) * 8u, pn);

                const int pos = 8 * c;
#pragma unroll
                for (int j = 0; j < CH; ++j) {
                    const int pr = j & 1;          // read parity ((t-1)&1)
                    const int pw = (j + 1) & 1;    // write parity (t&1)

                    // Halo: old la1 of column 2*tid-1.
                    float P1 = __shfl_up_sync(FULL, la1, 1);
                    const float hv = (w > 0) ? halo_s[pr][w - 1] : NEGF;
                    if (lane == 0) P1 = hv;

                    const float t1 = lse3_2(la1, la0, sk1 ? P1 : NEGF);
                    const float t0 = lse2_2(la0, P1);
                    la1 = fmaf(erl, LOG2E, t1);
                    la0 = fmaf(erb, LOG2E, t0);

                    if (lane == 31) halo_s[pw][w] = la1;
                    cbar();

                    // Stage row t+1.
                    const int rr = (pos + 1 + j) & 31;
                    erl = ring_l[rr][tid];
                    erb = ring_b[rr];
                }
                if (tid == 0) mbar_arrive(mb0 + (unsigned)(4 + c) * 8u);
                tb += CH;
            }
        }

        // ---- Tail: remaining < 32 steps, direct global loads -----------------
        for (int t = tb; t < il; ++t) {
            const float el = __ldg(pl + (size_t)t * strideT);
            const float eb = __ldg(rowbase + (size_t)t * strideT);

            const int pr = (t - 1) & 1;
            const int pw = t & 1;

            float P1 = __shfl_up_sync(FULL, la1, 1);
            const float hv = (w > 0) ? halo_s[pr][w - 1] : NEGF;
            if (lane == 0) P1 = hv;

            const float t1 = lse3_2(la1, la0, sk1 ? P1 : NEGF);
            const float t0 = lse2_2(la0, P1);
            la1 = fmaf(el, LOG2E, t1);
            la0 = fmaf(eb, LOG2E, t0);

            if (lane == 31) halo_s[pw][w] = la1;
            cbar();
        }

        // ---- Final cells: col 2*tl (thread tl), col 2*tl-1 (thread tl-1) -----
        if (tid == tl) fin[0] = la0;
        if (tl >= 1 && tid == tl - 1) fin[1] = la1;
        cbar();

        if (tid == 0) {
            const float x1 = fin[0];
            const float x2 = fin[1];
            const float m  = fmaxf(x1, x2);
            float loss = -LN2 * (m + lg2f(ex2f(x1 - m) + ex2f(x2 - m)));
            if (!(loss < 5.0e29f)) loss = 0.0f;    // zero_infinity
            g_loss[b] = loss;
            __threadfence();
            const unsigned n = atomicAdd(&g_done, 1u);
            if (n == (unsigned)(gridDim.x - 1)) s_last = 1;
        }
        cbar();

        if (s_last && w == 0) {
            float s = 0.0f;
            for (int i = lane; i < B; i += 32) s += g_loss[i];
#pragma unroll
            for (int o = 16; o; o >>= 1) s += __shfl_xor_sync(FULL, s, o);
            if (lane == 0) {
                out[0] = s;
                g_done = 0u;
            }
        }
    } else {
        // ===================== PRODUCER PATH (warp 4) =========================
        // Lane handles label slots {lane, lane+32, lane+64, lane+96} and the
        // blank value of row j==lane within each chunk.
        int offs[4];
#pragma unroll
        for (int q = 0; q < 4; ++q) {
            const int s = lane + 32 * q;
            offs[q] = (s < S) ? targets[b * S + s] : 0;
        }

        __syncthreads();                      // mbar init visible

        const int nchunks = (Rr > 0) ? 4 * Rr + 4 : 0;   // one extra round for staging
        for (int n = 0; n < nchunks; ++n) {
            const int c = n & 3;
            if (n >= 4) mbar_wait(mb0 + (unsigned)(4 + c) * 8u,
                                  (unsigned)(((n >> 2) - 1) & 1));
#pragma unroll
            for (int j = 0; j < CH; ++j) {
                int row = 8 * n + 1 + j;
                row = min(row, il - 1);
                const float* rp = rowbase + (size_t)row * strideT;
                const int rr = 8 * c + j;
#pragma unroll
                for (int q = 0; q < 4; ++q)
                    cp4(rl0 + (uint32_t)(rr * 128 + lane + 32 * q) * 4u, rp + offs[q]);
                if (lane == j) cp4(rb0 + (uint32_t)rr * 4u, rp);   // blank (class 0)
            }
            cp_wait_all();
            mbar_arrive(mb0 + (unsigned)c * 8u);   // full[c]: 32 arrivals
        }
    }
}

extern "C" void kernel_launch(void* const* d_in, const int* in_sizes, int n_in,
                              void* d_out, int out_size)
{
    const float* logp        = (const float*)d_in[0];
    const int*   targets     = (const int*)  d_in[1];
    const int*   input_lens  = (const int*)  d_in[2];
    const int*   target_lens = (const int*)  d_in[3];

    const int B = in_sizes[2];
    const int S = in_sizes[1] / B;
    const int C = 1000;                   // class count (dataset constant)

    ctc_fused_kernel<<<B, TPB>>>(logp, targets, input_lens, target_lens,
                                 (float*)d_out, B, C, S);
}